// round 1
// baseline (speedup 1.0000x reference)
#include <cuda_runtime.h>
#include <math.h>

#define SEQ     65536
#define FEAT    512
#define NTH     1024
#define CHUNK   64            // SEQ / NTH
#define THRES1  0.8f
#define THRES_UP 0.5f
#define MAXF    60

__device__ float g_a[SEQ];    // sigmoid(h@W + b), scratch

// ---------------------------------------------------------------------------
// Kernel 1: a[r] = sigmoid(dot(h[r,:], W) + b).  One warp per row.
// ---------------------------------------------------------------------------
__global__ void gemv_sigmoid_kernel(const float* __restrict__ h,
                                    const float* __restrict__ W,
                                    const float* __restrict__ b) {
    __shared__ float4 sW[FEAT / 4];
    for (int i = threadIdx.x; i < FEAT / 4; i += blockDim.x)
        sW[i] = ((const float4*)W)[i];
    __syncthreads();

    int row  = (int)((blockIdx.x * blockDim.x + threadIdx.x) >> 5);
    int lane = threadIdx.x & 31;
    if (row >= SEQ) return;

    const float4* hr = (const float4*)(h + (size_t)row * FEAT);
    float sum = 0.f;
#pragma unroll
    for (int k = 0; k < FEAT / 128; k++) {
        float4 hv = hr[lane + 32 * k];
        float4 wv = sW[lane + 32 * k];
        sum += hv.x * wv.x + hv.y * wv.y + hv.z * wv.z + hv.w * wv.w;
    }
#pragma unroll
    for (int d = 16; d; d >>= 1) sum += __shfl_down_sync(0xffffffffu, sum, d);
    if (lane == 0) g_a[row] = 1.f / (1.f + expf(-(sum + b[0])));
}

// ---------------------------------------------------------------------------
// Kernel 2: the full TGNN scan, single block of 1024 threads, 64 elems each.
// ---------------------------------------------------------------------------
__global__ void __launch_bounds__(NTH, 1)
tgnn_scan_kernel(const float* __restrict__ u_pred,
                 const float* __restrict__ label,
                 const float* __restrict__ thres2,
                 float* __restrict__ out, int out_size) {
    __shared__ float sA[32], sB[32];
    __shared__ float s_state[NTH];

    const int tid  = threadIdx.x;
    const int lane = tid & 31;
    const int wid  = tid >> 5;
    const int base = tid * CHUNK;

    float* ys     = out;
    float* alphas = out + SEQ;
    float* upcopy = out + 2 * SEQ;
    float* uphats = out + 3 * SEQ;

    // ================= Stage A: up_hat (segmented running max) =============
    // transform: state m (-1 = "low", else current-run max)
    //   encode chunk transform as (f, v): m_out = f ? max(m_in, v) : v
    {
        float f = 1.f, v = -1.f;
        for (int i = 0; i < CHUNK; i++) {
            float u = u_pred[base + i];
            if (u >= THRES_UP) v = fmaxf(v, u);
            else { f = 0.f; v = -1.f; }
        }
        // warp inclusive scan: compose earlier(ff,vv) then current(f,v)
#pragma unroll
        for (int d = 1; d < 32; d <<= 1) {
            float ff = __shfl_up_sync(0xffffffffu, f, d);
            float vv = __shfl_up_sync(0xffffffffu, v, d);
            if (lane >= d) { v = (f != 0.f) ? fmaxf(vv, v) : v; f *= ff; }
        }
        if (lane == 31) { sA[wid] = f; sB[wid] = v; }
        __syncthreads();
        if (wid == 0) {
            float F = sA[lane], V = sB[lane];
#pragma unroll
            for (int d = 1; d < 32; d <<= 1) {
                float ff = __shfl_up_sync(0xffffffffu, F, d);
                float vv = __shfl_up_sync(0xffffffffu, V, d);
                if (lane >= d) { V = (F != 0.f) ? fmaxf(vv, V) : V; F *= ff; }
            }
            sA[lane] = F; sB[lane] = V;
        }
        __syncthreads();
        if (wid > 0) {
            float fp = sA[wid - 1], vp = sB[wid - 1];
            v = (f != 0.f) ? fmaxf(vp, v) : v;
            f *= fp;
        }
        __syncthreads();
        s_state[tid] = v;   // applied to initial state -1 this is just v
        __syncthreads();
        float m = (tid == 0) ? -1.f : s_state[tid - 1];

        for (int i = 0; i < CHUNK; i++) {
            float u = u_pred[base + i];
            float uh;
            if (u >= THRES_UP) { m = fmaxf(m, u); uh = m; }
            else               { m = -1.f;        uh = u; }
            uphats[base + i] = uh;
            upcopy[base + i] = u;
        }
    }
    __syncthreads();

    // ================= Stage B: alpha (linear scan) =========================
    // alpha_i = c*alpha_{i-1} + (1-c)*a_i,  c = up_hat_i
    {
        float p = 1.f, q = 0.f;
        for (int i = 0; i < CHUNK; i++) {
            float c = uphats[base + i];
            float a = g_a[base + i];
            q = c * q + (1.f - c) * a;
            p = c * p;
        }
#pragma unroll
        for (int d = 1; d < 32; d <<= 1) {
            float pp = __shfl_up_sync(0xffffffffu, p, d);
            float qq = __shfl_up_sync(0xffffffffu, q, d);
            if (lane >= d) { q = p * qq + q; p *= pp; }
        }
        if (lane == 31) { sA[wid] = p; sB[wid] = q; }
        __syncthreads();
        if (wid == 0) {
            float P = sA[lane], Q = sB[lane];
#pragma unroll
            for (int d = 1; d < 32; d <<= 1) {
                float pp = __shfl_up_sync(0xffffffffu, P, d);
                float qq = __shfl_up_sync(0xffffffffu, Q, d);
                if (lane >= d) { Q = P * qq + Q; P *= pp; }
            }
            sA[lane] = P; sB[lane] = Q;
        }
        __syncthreads();
        if (wid > 0) { q = p * sB[wid - 1] + q; p *= sA[wid - 1]; }
        __syncthreads();
        s_state[tid] = q;   // applied to alpha_{-1} = 0
        __syncthreads();
        float al = (tid == 0) ? 0.f : s_state[tid - 1];

        for (int i = 0; i < CHUNK; i++) {
            float c = uphats[base + i];
            float a = g_a[base + i];
            al = c * al + (1.f - c) * a;
            alphas[base + i] = al;
        }
    }
    __syncthreads();

    // ================= Stage C: y (linear scan with resets) =================
    // high: y = alpha*up_hat + (1-alpha)*y_prev   low: y = 0
    {
        float p = 1.f, q = 0.f;
        for (int i = 0; i < CHUNK; i++) {
            float uh = uphats[base + i];
            float al = alphas[base + i];
            float A, B;
            if (uh >= THRES_UP) { A = 1.f - al; B = al * uh; }
            else                { A = 0.f;      B = 0.f; }
            q = A * q + B;
            p = A * p;
        }
#pragma unroll
        for (int d = 1; d < 32; d <<= 1) {
            float pp = __shfl_up_sync(0xffffffffu, p, d);
            float qq = __shfl_up_sync(0xffffffffu, q, d);
            if (lane >= d) { q = p * qq + q; p *= pp; }
        }
        if (lane == 31) { sA[wid] = p; sB[wid] = q; }
        __syncthreads();
        if (wid == 0) {
            float P = sA[lane], Q = sB[lane];
#pragma unroll
            for (int d = 1; d < 32; d <<= 1) {
                float pp = __shfl_up_sync(0xffffffffu, P, d);
                float qq = __shfl_up_sync(0xffffffffu, Q, d);
                if (lane >= d) { Q = P * qq + Q; P *= pp; }
            }
            sA[lane] = P; sB[lane] = Q;
        }
        __syncthreads();
        if (wid > 0) { q = p * sB[wid - 1] + q; p *= sA[wid - 1]; }
        __syncthreads();
        s_state[tid] = q;
        __syncthreads();
        float y = (tid == 0) ? 0.f : s_state[tid - 1];

        for (int i = 0; i < CHUNK; i++) {
            float uh = uphats[base + i];
            float al = alphas[base + i];
            if (uh >= THRES_UP) y = al * uh + (1.f - al) * y;
            else                y = 0.f;
            ys[base + i] = y;
        }
    }
    __syncthreads();   // ys must be globally visible for cross-chunk y_pre reads

    // ================= Stage D: l_c / loss / cnt ===========================
    {
        float lcf = 1.f;   // 1 = l_c still unknown (pass-through)
        float lcv = 0.f;
        float loss_loc = 0.f;
        float cnt_loc  = 0.f;
        int   defer    = -1;   // at most one deferred fall per chunk

        float uprev = (base == 0) ? 0.f : u_pred[base - 1];
        for (int i = 0; i < CHUNK; i++) {
            int   idx = base + i;
            float u   = u_pred[idx];
            float lab = label[idx];
            if (lab >= THRES1) {
                if (u < THRES_UP) lcv = -1.f;
                else {
                    float yv = ys[idx];
                    float dd = yv - lab;
                    lcv = dd * dd;
                }
                lcf = 0.f;
            }
            bool fall = (uprev >= THRES_UP) && (u < THRES_UP);
            if (fall) {
                if (lcf == 0.f) {
                    float lc   = lcv;
                    float ypre = ys[idx - 1];   // fall implies idx >= 1
                    bool isneg = (lc == -1.f);
                    bool nz    = (lc != 0.f);
                    if (!isneg && nz) { loss_loc += lc; cnt_loc += 1.f; }
                    else if (!isneg && !nz) {
                        if (ypre >= THRES1) {
                            float t2 = thres2[idx < MAXF - 1 ? idx : MAXF - 1];
                            float d  = ypre - t2;
                            loss_loc += d * d;
                            cnt_loc  += 1.f;
                        }
                    }
                } else {
                    defer = idx;
                }
                lcv = 0.f; lcf = 0.f;
            }
            uprev = u;
        }

        // scan of (lcf, lcv): later-wins select
        float f = lcf, v = lcv;
#pragma unroll
        for (int d = 1; d < 32; d <<= 1) {
            float ff = __shfl_up_sync(0xffffffffu, f, d);
            float vv = __shfl_up_sync(0xffffffffu, v, d);
            if (lane >= d) { v = (f != 0.f) ? vv : v; f *= ff; }
        }
        if (lane == 31) { sA[wid] = f; sB[wid] = v; }
        __syncthreads();
        if (wid == 0) {
            float F = sA[lane], V = sB[lane];
#pragma unroll
            for (int d = 1; d < 32; d <<= 1) {
                float ff = __shfl_up_sync(0xffffffffu, F, d);
                float vv = __shfl_up_sync(0xffffffffu, V, d);
                if (lane >= d) { V = (F != 0.f) ? vv : V; F *= ff; }
            }
            sA[lane] = F; sB[lane] = V;
        }
        __syncthreads();
        if (wid > 0) {
            float fp = sA[wid - 1], vp = sB[wid - 1];
            v = (f != 0.f) ? vp : v;
            f *= fp;
        }
        __syncthreads();
        s_state[tid] = (f != 0.f) ? 0.f : v;   // applied to initial l_c = 0
        __syncthreads();
        float lc_in = (tid == 0) ? 0.f : s_state[tid - 1];

        if (defer >= 0) {
            float lc   = lc_in;
            float ypre = ys[defer - 1];
            bool isneg = (lc == -1.f);
            bool nz    = (lc != 0.f);
            if (!isneg && nz) { loss_loc += lc; cnt_loc += 1.f; }
            else if (!isneg && !nz) {
                if (ypre >= THRES1) {
                    float t2 = thres2[defer < MAXF - 1 ? defer : MAXF - 1];
                    float d  = ypre - t2;
                    loss_loc += d * d;
                    cnt_loc  += 1.f;
                }
            }
        }
        __syncthreads();

        // deterministic tree reductions for loss and cnt
        s_state[tid] = loss_loc;
        __syncthreads();
        for (int s = NTH / 2; s > 0; s >>= 1) {
            if (tid < s) s_state[tid] += s_state[tid + s];
            __syncthreads();
        }
        float total_loss = s_state[0];
        __syncthreads();

        s_state[tid] = cnt_loc;
        __syncthreads();
        for (int s = NTH / 2; s > 0; s >>= 1) {
            if (tid < s) s_state[tid] += s_state[tid + s];
            __syncthreads();
        }
        float total_cnt = s_state[0];

        if (tid == 0 && out_size >= 4 * SEQ + 2) {
            out[4 * SEQ]     = total_loss;
            out[4 * SEQ + 1] = total_cnt;
        }
    }
}

// ---------------------------------------------------------------------------
extern "C" void kernel_launch(void* const* d_in, const int* in_sizes, int n_in,
                              void* d_out, int out_size) {
    const float* h      = (const float*)d_in[0];
    const float* W      = (const float*)d_in[1];
    const float* b      = (const float*)d_in[2];
    // d_in[3] = u (unused, as in reference)
    const float* u_pred = (const float*)d_in[4];
    const float* label  = (const float*)d_in[5];
    const float* thres2 = (const float*)d_in[6];
    float* out = (float*)d_out;

    // one warp per row: 65536 warps -> 8192 blocks x 256 threads
    gemv_sigmoid_kernel<<<SEQ / 8, 256>>>(h, W, b);
    tgnn_scan_kernel<<<1, NTH>>>(u_pred, label, thres2, out, out_size);
}

// round 2
// speedup vs baseline: 12.9609x; 12.9609x over previous
#include <cuda_runtime.h>
#include <math.h>

#define SEQ      65536
#define FEAT     512
#define NB       128          // number of tiles / blocks
#define TPB      128          // threads per block
#define EPT      4            // elements per thread
#define THRES1   0.8f
#define THRES_UP 0.5f
#define MAXF     60

__device__ float g_a[SEQ];

__device__ float g_mf[NB], g_mv[NB], g_min[NB];
__device__ float g_ap[NB], g_aq[NB], g_ain[NB];
__device__ float g_yp[NB], g_yq[NB], g_yin[NB];
__device__ float g_lf[NB], g_lv[NB], g_loss[NB], g_cnt[NB];
__device__ int   g_didx[NB];
__device__ float g_dypre[NB];

// ---------------------------------------------------------------------------
// transform composition: result = later(t2) ∘ earlier(t1), stored into t2.
// OP 0: segmented max   state: m -> f? max(m,v) : v
// OP 1: linear          state: x -> f*x + v
// OP 2: last-set select state: x -> f? x : v
// ---------------------------------------------------------------------------
template<int OP>
__device__ __forceinline__ void comb(float f1, float v1, float& f2, float& v2) {
    if (OP == 0) { v2 = (f2 != 0.f) ? fmaxf(v1, v2) : v2; f2 = f1 * f2; }
    if (OP == 1) { v2 = f2 * v1 + v2;                      f2 = f1 * f2; }
    if (OP == 2) { v2 = (f2 != 0.f) ? v1 : v2;             f2 = f1 * f2; }
}

// Block-wide (128 threads = 4 warps) EXCLUSIVE scan of per-thread transforms.
// Returns exclusive prefix (fex,vex) and block total (ftot,vtot).
template<int OP>
__device__ void blk_scan_excl(float f, float v, float idv,
                              float& fex, float& vex,
                              float& ftot, float& vtot,
                              float* sf, float* sv) {
    int lane = threadIdx.x & 31, w = threadIdx.x >> 5;
#pragma unroll
    for (int d = 1; d < 32; d <<= 1) {
        float ff = __shfl_up_sync(0xffffffffu, f, d);
        float vv = __shfl_up_sync(0xffffffffu, v, d);
        if (lane >= d) comb<OP>(ff, vv, f, v);
    }
    __syncthreads();                 // protect smem reuse across calls
    if (lane == 31) { sf[w] = f; sv[w] = v; }
    __syncthreads();
    // exclusive warp prefix (serial over <=3)
    float pf = 1.f, pv = idv;
    for (int i = 0; i < w; i++) {
        float cf = sf[i], cv = sv[i];
        comb<OP>(pf, pv, cf, cv);
        pf = cf; pv = cv;
    }
    // block total
    float tf = 1.f, tv = idv;
#pragma unroll
    for (int i = 0; i < 4; i++) {
        float cf = sf[i], cv = sv[i];
        comb<OP>(tf, tv, cf, cv);
        tf = cf; tv = cv;
    }
    ftot = tf; vtot = tv;
    // lane-exclusive within warp, then prepend warp prefix
    float lf = __shfl_up_sync(0xffffffffu, f, 1);
    float lv = __shfl_up_sync(0xffffffffu, v, 1);
    if (lane == 0) { lf = 1.f; lv = idv; }
    comb<OP>(pf, pv, lf, lv);
    fex = lf; vex = lv;
}

// Ordered (non-commutative) block reduce of transforms -> thread 0 writes.
template<int OP>
__device__ void blk_reduce_write(float f, float v, float idv, int b,
                                 float* gf, float* gv, float* sf, float* sv) {
    int lane = threadIdx.x & 31, w = threadIdx.x >> 5;
#pragma unroll
    for (int d = 1; d < 32; d <<= 1) {
        float ff = __shfl_down_sync(0xffffffffu, f, d);
        float vv = __shfl_down_sync(0xffffffffu, v, d);
        comb<OP>(f, v, ff, vv);      // (ff,vv) = later segment ∘ mine
        f = ff; v = vv;
    }
    __syncthreads();
    if (lane == 0) { sf[w] = f; sv[w] = v; }
    __syncthreads();
    if (threadIdx.x == 0) {
        float tf = 1.f, tv = idv;
#pragma unroll
        for (int i = 0; i < 4; i++) {
            float cf = sf[i], cv = sv[i];
            comb<OP>(tf, tv, cf, cv);
            tf = cf; tv = cv;
        }
        gf[b] = tf; gv[b] = tv;
    }
}

// ---------------------------------------------------------------------------
// GEMV + sigmoid: one warp per row.
// ---------------------------------------------------------------------------
__global__ void gemv_sigmoid_kernel(const float* __restrict__ h,
                                    const float* __restrict__ W,
                                    const float* __restrict__ b) {
    __shared__ float4 sW[FEAT / 4];
    for (int i = threadIdx.x; i < FEAT / 4; i += blockDim.x)
        sW[i] = ((const float4*)W)[i];
    __syncthreads();

    int row  = (int)((blockIdx.x * blockDim.x + threadIdx.x) >> 5);
    int lane = threadIdx.x & 31;
    const float4* hr = (const float4*)(h + (size_t)row * FEAT);
    float sum = 0.f;
#pragma unroll
    for (int k = 0; k < FEAT / 128; k++) {
        float4 hv = hr[lane + 32 * k];
        float4 wv = sW[lane + 32 * k];
        sum += hv.x * wv.x + hv.y * wv.y + hv.z * wv.z + hv.w * wv.w;
    }
#pragma unroll
    for (int d = 16; d; d >>= 1) sum += __shfl_down_sync(0xffffffffu, sum, d);
    if (lane == 0) g_a[row] = 1.f / (1.f + expf(-(sum + b[0])));
}

// ---------------------------------------------------------------------------
// K_A: per-tile (f,v) partial for the up_hat segmented max scan.
// ---------------------------------------------------------------------------
__global__ void __launch_bounds__(TPB)
k_mpart(const float* __restrict__ up) {
    __shared__ float sf[4], sv[4];
    int gi = blockIdx.x * TPB + threadIdx.x;
    float4 u4 = ((const float4*)up)[gi];
    float ue[4] = {u4.x, u4.y, u4.z, u4.w};
    float f = 1.f, v = -1.f;
#pragma unroll
    for (int e = 0; e < 4; e++) {
        if (ue[e] >= THRES_UP) v = fmaxf(v, ue[e]);
        else { f = 0.f; v = -1.f; }
    }
    blk_reduce_write<0>(f, v, -1.f, blockIdx.x, g_mf, g_mv, sf, sv);
}

// K_B: 1-block exclusive scan of 128 tile transforms -> incoming m per tile.
__global__ void __launch_bounds__(NB)
k_scan_m() {
    __shared__ float sf[4], sv[4];
    int t = threadIdx.x;
    float fex, vex, ft, vt;
    blk_scan_excl<0>(g_mf[t], g_mv[t], -1.f, fex, vex, ft, vt, sf, sv);
    g_min[t] = vex;     // applied to initial m = -1 this is always vex
}

// ---------------------------------------------------------------------------
// K_C: apply m carry -> up_hat (write), compute alpha (p,q) tile partial.
// ---------------------------------------------------------------------------
__global__ void __launch_bounds__(TPB)
k_uphat_apart(const float* __restrict__ up, float* __restrict__ out) {
    __shared__ float sf[4], sv[4];
    int b = blockIdx.x, gi = b * TPB + threadIdx.x;
    float4 u4 = ((const float4*)up)[gi];
    float ue[4] = {u4.x, u4.y, u4.z, u4.w};

    float f = 1.f, v = -1.f;
#pragma unroll
    for (int e = 0; e < 4; e++) {
        if (ue[e] >= THRES_UP) v = fmaxf(v, ue[e]);
        else { f = 0.f; v = -1.f; }
    }
    float fex, vex, ft, vt;
    blk_scan_excl<0>(f, v, -1.f, fex, vex, ft, vt, sf, sv);

    float m = (fex != 0.f) ? fmaxf(g_min[b], vex) : vex;
    float uh[4];
#pragma unroll
    for (int e = 0; e < 4; e++) {
        if (ue[e] >= THRES_UP) { m = fmaxf(m, ue[e]); uh[e] = m; }
        else                   { m = -1.f;            uh[e] = ue[e]; }
    }
    ((float4*)(out + 3 * SEQ))[gi] = make_float4(uh[0], uh[1], uh[2], uh[3]);

    float4 a4 = ((const float4*)g_a)[gi];
    float ae[4] = {a4.x, a4.y, a4.z, a4.w};
    float p = 1.f, q = 0.f;
#pragma unroll
    for (int e = 0; e < 4; e++) {
        q = uh[e] * q + (1.f - uh[e]) * ae[e];
        p = uh[e] * p;
    }
    blk_reduce_write<1>(p, q, 0.f, b, g_ap, g_aq, sf, sv);
}

__global__ void __launch_bounds__(NB)
k_scan_a() {
    __shared__ float sf[4], sv[4];
    int t = threadIdx.x;
    float fex, vex, ft, vt;
    blk_scan_excl<1>(g_ap[t], g_aq[t], 0.f, fex, vex, ft, vt, sf, sv);
    g_ain[t] = vex;     // applied to alpha_{-1} = 0
}

// ---------------------------------------------------------------------------
// K_E: apply alpha carry -> alphas (write), compute y (p,q) tile partial.
// ---------------------------------------------------------------------------
__global__ void __launch_bounds__(TPB)
k_alpha_ypart(float* __restrict__ out) {
    __shared__ float sf[4], sv[4];
    int b = blockIdx.x, gi = b * TPB + threadIdx.x;
    float4 uh4 = ((const float4*)(out + 3 * SEQ))[gi];
    float uh[4] = {uh4.x, uh4.y, uh4.z, uh4.w};
    float4 a4 = ((const float4*)g_a)[gi];
    float ae[4] = {a4.x, a4.y, a4.z, a4.w};

    float p = 1.f, q = 0.f;
#pragma unroll
    for (int e = 0; e < 4; e++) {
        q = uh[e] * q + (1.f - uh[e]) * ae[e];
        p = uh[e] * p;
    }
    float fex, vex, ft, vt;
    blk_scan_excl<1>(p, q, 0.f, fex, vex, ft, vt, sf, sv);

    float al = fex * g_ain[b] + vex;
    float alv[4];
#pragma unroll
    for (int e = 0; e < 4; e++) {
        al = uh[e] * al + (1.f - uh[e]) * ae[e];
        alv[e] = al;
    }
    ((float4*)(out + SEQ))[gi] = make_float4(alv[0], alv[1], alv[2], alv[3]);

    // y partial
    float yp = 1.f, yq = 0.f;
#pragma unroll
    for (int e = 0; e < 4; e++) {
        float A, B;
        if (uh[e] >= THRES_UP) { A = 1.f - alv[e]; B = alv[e] * uh[e]; }
        else                   { A = 0.f;          B = 0.f; }
        yq = A * yq + B;
        yp = A * yp;
    }
    blk_reduce_write<1>(yp, yq, 0.f, b, g_yp, g_yq, sf, sv);
}

__global__ void __launch_bounds__(NB)
k_scan_y() {
    __shared__ float sf[4], sv[4];
    int t = threadIdx.x;
    float fex, vex, ft, vt;
    blk_scan_excl<1>(g_yp[t], g_yq[t], 0.f, fex, vex, ft, vt, sf, sv);
    g_yin[t] = vex;     // applied to y_{-1} = 0
}

// ---------------------------------------------------------------------------
// K_G: apply y carry -> ys (write); stage D local loss/cnt + l_c transforms.
// ---------------------------------------------------------------------------
__device__ __forceinline__ void resolve_fall(float lc, float ypre, int gidx,
                                             const float* __restrict__ th2,
                                             float& loss, float& cnt) {
    bool isneg = (lc == -1.f);
    bool nz    = (lc != 0.f);
    if (!isneg && nz) { loss += lc; cnt += 1.f; }           // * R (R=1)
    else if (!isneg && !nz && ypre >= THRES1) {
        float t2 = th2[gidx < MAXF - 1 ? gidx : MAXF - 1];
        float d = ypre - t2;
        loss += d * d; cnt += 1.f;
    }
}

__global__ void __launch_bounds__(TPB)
k_y_stageD(const float* __restrict__ up, const float* __restrict__ lab,
           const float* __restrict__ th2, float* __restrict__ out) {
    __shared__ float sf[4], sv[4];
    __shared__ int   s_didx;
    __shared__ float s_dypre;
    int b = blockIdx.x, gi = b * TPB + threadIdx.x;

    float4 uh4 = ((const float4*)(out + 3 * SEQ))[gi];
    float uh[4] = {uh4.x, uh4.y, uh4.z, uh4.w};
    float4 al4 = ((const float4*)(out + SEQ))[gi];
    float alv[4] = {al4.x, al4.y, al4.z, al4.w};

    float yp = 1.f, yq = 0.f;
#pragma unroll
    for (int e = 0; e < 4; e++) {
        float A, B;
        if (uh[e] >= THRES_UP) { A = 1.f - alv[e]; B = alv[e] * uh[e]; }
        else                   { A = 0.f;          B = 0.f; }
        yq = A * yq + B;
        yp = A * yp;
    }
    float fex, vex, ft, vt;
    blk_scan_excl<1>(yp, yq, 0.f, fex, vex, ft, vt, sf, sv);

    float y = fex * g_yin[b] + vex;     // y_pre entering this thread's chunk

    float4 u4 = ((const float4*)up)[gi];
    float ue[4] = {u4.x, u4.y, u4.z, u4.w};
    float4 l4 = ((const float4*)lab)[gi];
    float le[4] = {l4.x, l4.y, l4.z, l4.w};

    int  gbase = gi * 4;
    float uprev = (gbase == 0) ? 0.f : up[gbase - 1];

    float lcf = 1.f, lcv = 0.f, loss = 0.f, cnt = 0.f;
    int   didx = -1;
    float dypre = 0.f;
    float yv[4];
    float ypre = y;
#pragma unroll
    for (int e = 0; e < 4; e++) {
        float ynew = (uh[e] >= THRES_UP) ? (alv[e] * uh[e] + (1.f - alv[e]) * ypre)
                                         : 0.f;
        yv[e] = ynew;
        if (le[e] >= THRES1) {
            lcv = (uh[e] < THRES_UP) ? -1.f : (ynew - le[e]) * (ynew - le[e]);
            lcf = 0.f;
        }
        bool fall = (uprev >= THRES_UP) && (ue[e] < THRES_UP);
        if (fall) {
            if (lcf == 0.f) resolve_fall(lcv, ypre, gbase + e, th2, loss, cnt);
            else            { didx = gbase + e; dypre = ypre; }
            lcv = 0.f; lcf = 0.f;
        }
        uprev = ue[e];
        ypre  = ynew;
    }
    ((float4*)out)[gi] = make_float4(yv[0], yv[1], yv[2], yv[3]);

    // in-block l_c scan; resolve thread defers whose prefix is known
    float fex2, vex2, ft2, vt2;
    blk_scan_excl<2>(lcf, lcv, 0.f, fex2, vex2, ft2, vt2, sf, sv);
    if (didx >= 0 && fex2 == 0.f) {
        resolve_fall(vex2, dypre, didx, th2, loss, cnt);
        didx = -1;
    }
    if (threadIdx.x == 0) { s_didx = -1; s_dypre = 0.f; }
    __syncthreads();
    if (didx >= 0) { s_didx = didx; s_dypre = dypre; }   // at most one thread
    __syncthreads();
    if (threadIdx.x == 0) {
        g_didx[b]  = s_didx;
        g_dypre[b] = s_dypre;
        g_lf[b]    = ft2;
        g_lv[b]    = vt2;
    }

    // sum-reduce loss & cnt (commutative)
    int lane = threadIdx.x & 31, w = threadIdx.x >> 5;
#pragma unroll
    for (int d = 16; d; d >>= 1) {
        loss += __shfl_down_sync(0xffffffffu, loss, d);
        cnt  += __shfl_down_sync(0xffffffffu, cnt,  d);
    }
    __syncthreads();
    if (lane == 0) { sf[w] = loss; sv[w] = cnt; }
    __syncthreads();
    if (threadIdx.x == 0) {
        g_loss[b] = sf[0] + sf[1] + sf[2] + sf[3];
        g_cnt[b]  = sv[0] + sv[1] + sv[2] + sv[3];
    }
}

// ---------------------------------------------------------------------------
// K_H: scan block l_c transforms, resolve block defers, reduce loss/cnt.
// ---------------------------------------------------------------------------
__global__ void __launch_bounds__(NB)
k_final(const float* __restrict__ th2, float* __restrict__ out, int out_size) {
    __shared__ float sf[4], sv[4];
    int t = threadIdx.x;
    float fex, vex, ft, vt;
    blk_scan_excl<2>(g_lf[t], g_lv[t], 0.f, fex, vex, ft, vt, sf, sv);
    float lc_in = (fex != 0.f) ? 0.f : vex;     // initial l_c = 0

    float loss = g_loss[t], cnt = g_cnt[t];
    int di = g_didx[t];
    if (di >= 0) resolve_fall(lc_in, g_dypre[t], di, th2, loss, cnt);

    int lane = t & 31, w = t >> 5;
#pragma unroll
    for (int d = 16; d; d >>= 1) {
        loss += __shfl_down_sync(0xffffffffu, loss, d);
        cnt  += __shfl_down_sync(0xffffffffu, cnt,  d);
    }
    __syncthreads();
    if (lane == 0) { sf[w] = loss; sv[w] = cnt; }
    __syncthreads();
    if (t == 0 && out_size >= 4 * SEQ + 2) {
        out[4 * SEQ]     = sf[0] + sf[1] + sf[2] + sf[3];
        out[4 * SEQ + 1] = sv[0] + sv[1] + sv[2] + sv[3];
    }
}

// ---------------------------------------------------------------------------
extern "C" void kernel_launch(void* const* d_in, const int* in_sizes, int n_in,
                              void* d_out, int out_size) {
    const float* h      = (const float*)d_in[0];
    const float* W      = (const float*)d_in[1];
    const float* b      = (const float*)d_in[2];
    // d_in[3] = u (unused in loss, copied nowhere — ref returns u_pred copy)
    const float* u_pred = (const float*)d_in[4];
    const float* label  = (const float*)d_in[5];
    const float* thres2 = (const float*)d_in[6];
    float* out = (float*)d_out;

    gemv_sigmoid_kernel<<<SEQ / 8, 256>>>(h, W, b);
    cudaMemcpyAsync(out + 2 * SEQ, u_pred, SEQ * sizeof(float),
                    cudaMemcpyDeviceToDevice);
    k_mpart<<<NB, TPB>>>(u_pred);
    k_scan_m<<<1, NB>>>();
    k_uphat_apart<<<NB, TPB>>>(u_pred, out);
    k_scan_a<<<1, NB>>>();
    k_alpha_ypart<<<NB, TPB>>>(out);
    k_scan_y<<<1, NB>>>();
    k_y_stageD<<<NB, TPB>>>(u_pred, label, thres2, out);
    k_final<<<1, NB>>>(thres2, out, out_size);
}

// round 3
// speedup vs baseline: 14.9828x; 1.1560x over previous
#include <cuda_runtime.h>
#include <math.h>

#define SEQ      65536
#define FEAT     512
#define NB       128          // blocks in fused scan kernel (<=148: co-resident)
#define TPB      128
#define THRES1   0.8f
#define THRES_UP 0.5f
#define MAXF     60

__device__ float g_a[SEQ];

__device__ float g_mf[NB], g_mv[NB];
__device__ float g_ap[NB], g_aq[NB];
__device__ float g_yp[NB], g_yq[NB];
__device__ float g_lf[NB], g_lv[NB], g_loss[NB], g_cnt[NB];
__device__ int   g_didx[NB];
__device__ float g_dypre[NB];

__device__ unsigned g_sync[4];
__device__ unsigned g_ack;

// ---------------------------------------------------------------------------
// transform composition: result = later(t2) ∘ earlier(t1), stored into t2.
// OP 0: segmented max   state: m -> f? max(m,v) : v
// OP 1: linear          state: x -> f*x + v
// OP 2: last-set select state: x -> f? x : v
// ---------------------------------------------------------------------------
template<int OP>
__device__ __forceinline__ void comb(float f1, float v1, float& f2, float& v2) {
    if (OP == 0) { v2 = (f2 != 0.f) ? fmaxf(v1, v2) : v2; f2 = f1 * f2; }
    if (OP == 1) { v2 = f2 * v1 + v2;                      f2 = f1 * f2; }
    if (OP == 2) { v2 = (f2 != 0.f) ? v1 : v2;             f2 = f1 * f2; }
}

// Block-wide (128 threads) EXCLUSIVE scan of per-thread transforms.
template<int OP>
__device__ void blk_scan_excl(float f, float v, float idv,
                              float& fex, float& vex,
                              float& ftot, float& vtot,
                              float* sf, float* sv) {
    int lane = threadIdx.x & 31, w = threadIdx.x >> 5;
#pragma unroll
    for (int d = 1; d < 32; d <<= 1) {
        float ff = __shfl_up_sync(0xffffffffu, f, d);
        float vv = __shfl_up_sync(0xffffffffu, v, d);
        if (lane >= d) comb<OP>(ff, vv, f, v);
    }
    __syncthreads();                 // protect smem reuse across calls
    if (lane == 31) { sf[w] = f; sv[w] = v; }
    __syncthreads();
    float pf = 1.f, pv = idv;        // exclusive warp prefix
    for (int i = 0; i < w; i++) {
        float cf = sf[i], cv = sv[i];
        comb<OP>(pf, pv, cf, cv);
        pf = cf; pv = cv;
    }
    float tf = 1.f, tv = idv;        // block total
#pragma unroll
    for (int i = 0; i < 4; i++) {
        float cf = sf[i], cv = sv[i];
        comb<OP>(tf, tv, cf, cv);
        tf = cf; tv = cv;
    }
    ftot = tf; vtot = tv;
    float lf = __shfl_up_sync(0xffffffffu, f, 1);
    float lv = __shfl_up_sync(0xffffffffu, v, 1);
    if (lane == 0) { lf = 1.f; lv = idv; }
    comb<OP>(pf, pv, lf, lv);
    fex = lf; vex = lv;
}

// Grid-wide barrier: all NB blocks co-resident, spin on L2 counter.
__device__ __forceinline__ void gsync(int idx) {
    __syncthreads();
    if (threadIdx.x == 0) {
        __threadfence();
        unsigned prev = atomicAdd(&g_sync[idx], 1u);
        if (prev + 1u < (unsigned)NB) {
            volatile unsigned* p = &g_sync[idx];
            while (*p < (unsigned)NB) { }
        }
        __threadfence();
    }
    __syncthreads();
}

// Cross-block exclusive prefix for THIS block: every thread scans the 128
// block transforms; thread t==blockIdx.x publishes its exclusive prefix.
template<int OP>
__device__ __forceinline__ void cross_carry(const float* gf, const float* gv,
                                            float idv, float* sf, float* sv,
                                            float* s_c) {
    float f = gf[threadIdx.x], v = gv[threadIdx.x];
    float fex, vex, ft, vt;
    blk_scan_excl<OP>(f, v, idv, fex, vex, ft, vt, sf, sv);
    if (threadIdx.x == (int)blockIdx.x) { s_c[0] = fex; s_c[1] = vex; }
    __syncthreads();
}

__device__ __forceinline__ void resolve_fall(float lc, float ypre, int gidx,
                                             const float* __restrict__ th2,
                                             float& loss, float& cnt) {
    bool isneg = (lc == -1.f);
    bool nz    = (lc != 0.f);
    if (!isneg && nz) { loss += lc; cnt += 1.f; }            // * R (R=1)
    else if (!isneg && !nz && ypre >= THRES1) {
        float t2 = th2[gidx < MAXF - 1 ? gidx : MAXF - 1];
        float d = ypre - t2;
        loss += d * d; cnt += 1.f;
    }
}

// ---------------------------------------------------------------------------
// GEMV + sigmoid: one warp per row (HBM-bound, needs full-chip occupancy).
// ---------------------------------------------------------------------------
__global__ void __launch_bounds__(256)
gemv_sigmoid_kernel(const float* __restrict__ h,
                    const float* __restrict__ W,
                    const float* __restrict__ b) {
    __shared__ float4 sW[FEAT / 4];
    for (int i = threadIdx.x; i < FEAT / 4; i += blockDim.x)
        sW[i] = ((const float4*)W)[i];
    __syncthreads();

    int row  = (int)((blockIdx.x * blockDim.x + threadIdx.x) >> 5);
    int lane = threadIdx.x & 31;
    const float4* hr = (const float4*)(h + (size_t)row * FEAT);
    float sum = 0.f;
#pragma unroll
    for (int k = 0; k < FEAT / 128; k++) {
        float4 hv = hr[lane + 32 * k];
        float4 wv = sW[lane + 32 * k];
        sum += hv.x * wv.x + hv.y * wv.y + hv.z * wv.z + hv.w * wv.w;
    }
#pragma unroll
    for (int d = 16; d; d >>= 1) sum += __shfl_down_sync(0xffffffffu, sum, d);
    if (lane == 0) g_a[row] = 1.f / (1.f + __expf(-(sum + b[0])));
}

// ---------------------------------------------------------------------------
// Fused scan: all 4 hierarchical scans + loss in ONE kernel, 4 grid syncs.
// Per-thread data lives in registers across all phases.
// ---------------------------------------------------------------------------
__global__ void __launch_bounds__(TPB, 1)
k_scan_fused(const float* __restrict__ up, const float* __restrict__ lab,
             const float* __restrict__ th2, float* __restrict__ out,
             int out_size) {
    __shared__ float sf[4], sv[4];
    __shared__ float s_c[2];
    __shared__ int   s_didx;
    __shared__ float s_dypre;

    const int b  = blockIdx.x;
    const int gi = b * TPB + threadIdx.x;

    // ================= Phase A: up_hat (segmented running max) =============
    float4 u4 = ((const float4*)up)[gi];
    float ue[4] = {u4.x, u4.y, u4.z, u4.w};
    ((float4*)(out + 2 * SEQ))[gi] = u4;            // u_pred copy output

    float f = 1.f, v = -1.f;
#pragma unroll
    for (int e = 0; e < 4; e++) {
        if (ue[e] >= THRES_UP) v = fmaxf(v, ue[e]);
        else { f = 0.f; v = -1.f; }
    }
    float fexA, vexA, ftA, vtA;
    blk_scan_excl<0>(f, v, -1.f, fexA, vexA, ftA, vtA, sf, sv);
    if (threadIdx.x == 0) { g_mf[b] = ftA; g_mv[b] = vtA; }
    gsync(0);
    cross_carry<0>(g_mf, g_mv, -1.f, sf, sv, s_c);
    float m_in = s_c[1];                            // applied to m=-1 -> carry v
    float m = (fexA != 0.f) ? fmaxf(m_in, vexA) : vexA;

    float uh[4];
#pragma unroll
    for (int e = 0; e < 4; e++) {
        if (ue[e] >= THRES_UP) { m = fmaxf(m, ue[e]); uh[e] = m; }
        else                   { m = -1.f;            uh[e] = ue[e]; }
    }
    ((float4*)(out + 3 * SEQ))[gi] = make_float4(uh[0], uh[1], uh[2], uh[3]);

    // ================= Phase B: alpha (linear scan) =========================
    float4 a4 = ((const float4*)g_a)[gi];
    float ae[4] = {a4.x, a4.y, a4.z, a4.w};
    float p = 1.f, q = 0.f;
#pragma unroll
    for (int e = 0; e < 4; e++) {
        q = uh[e] * q + (1.f - uh[e]) * ae[e];
        p = uh[e] * p;
    }
    float fexB, vexB, ftB, vtB;
    blk_scan_excl<1>(p, q, 0.f, fexB, vexB, ftB, vtB, sf, sv);
    if (threadIdx.x == 0) { g_ap[b] = ftB; g_aq[b] = vtB; }
    gsync(1);
    cross_carry<1>(g_ap, g_aq, 0.f, sf, sv, s_c);
    float al = fexB * s_c[1] + vexB;                // alpha entering this thread

    float alv[4];
#pragma unroll
    for (int e = 0; e < 4; e++) {
        al = uh[e] * al + (1.f - uh[e]) * ae[e];
        alv[e] = al;
    }
    ((float4*)(out + SEQ))[gi] = make_float4(alv[0], alv[1], alv[2], alv[3]);

    // ================= Phase C: y (linear scan with resets) =================
    float yp = 1.f, yq = 0.f;
#pragma unroll
    for (int e = 0; e < 4; e++) {
        float A = 0.f, B = 0.f;
        if (uh[e] >= THRES_UP) { A = 1.f - alv[e]; B = alv[e] * uh[e]; }
        yq = A * yq + B;
        yp = A * yp;
    }
    float fexC, vexC, ftC, vtC;
    blk_scan_excl<1>(yp, yq, 0.f, fexC, vexC, ftC, vtC, sf, sv);
    if (threadIdx.x == 0) { g_yp[b] = ftC; g_yq[b] = vtC; }
    gsync(2);
    cross_carry<1>(g_yp, g_yq, 0.f, sf, sv, s_c);
    float y = fexC * s_c[1] + vexC;                 // y_pre entering this thread

    // ================= Phase D: y values + l_c / loss / cnt ================
    float4 l4 = ((const float4*)lab)[gi];
    float le[4] = {l4.x, l4.y, l4.z, l4.w};

    int   gbase = gi * 4;
    float uprev = (gbase == 0) ? 0.f : up[gbase - 1];

    float lcf = 1.f, lcv = 0.f, loss = 0.f, cnt = 0.f;
    int   didx = -1;
    float dypre = 0.f;
    float yv[4];
    float ypre = y;
#pragma unroll
    for (int e = 0; e < 4; e++) {
        float ynew = (uh[e] >= THRES_UP) ? (alv[e] * uh[e] + (1.f - alv[e]) * ypre)
                                         : 0.f;
        yv[e] = ynew;
        if (le[e] >= THRES1) {
            lcv = (uh[e] < THRES_UP) ? -1.f : (ynew - le[e]) * (ynew - le[e]);
            lcf = 0.f;
        }
        bool fall = (uprev >= THRES_UP) && (ue[e] < THRES_UP);
        if (fall) {
            if (lcf == 0.f) resolve_fall(lcv, ypre, gbase + e, th2, loss, cnt);
            else            { didx = gbase + e; dypre = ypre; }
            lcv = 0.f; lcf = 0.f;
        }
        uprev = ue[e];
        ypre  = ynew;
    }
    ((float4*)out)[gi] = make_float4(yv[0], yv[1], yv[2], yv[3]);

    // in-block l_c scan; resolve thread defers whose prefix is known
    float fex2, vex2, ft2, vt2;
    blk_scan_excl<2>(lcf, lcv, 0.f, fex2, vex2, ft2, vt2, sf, sv);
    if (didx >= 0 && fex2 == 0.f) {
        resolve_fall(vex2, dypre, didx, th2, loss, cnt);
        didx = -1;
    }
    if (threadIdx.x == 0) { s_didx = -1; s_dypre = 0.f; }
    __syncthreads();
    if (didx >= 0) { s_didx = didx; s_dypre = dypre; }   // at most one thread
    __syncthreads();
    if (threadIdx.x == 0) {
        g_didx[b]  = s_didx;
        g_dypre[b] = s_dypre;
        g_lf[b]    = ft2;
        g_lv[b]    = vt2;
    }

    // block loss/cnt sums
    int lane = threadIdx.x & 31, w = threadIdx.x >> 5;
#pragma unroll
    for (int d = 16; d; d >>= 1) {
        loss += __shfl_down_sync(0xffffffffu, loss, d);
        cnt  += __shfl_down_sync(0xffffffffu, cnt,  d);
    }
    __syncthreads();
    if (lane == 0) { sf[w] = loss; sv[w] = cnt; }
    __syncthreads();
    if (threadIdx.x == 0) {
        g_loss[b] = sf[0] + sf[1] + sf[2] + sf[3];
        g_cnt[b]  = sv[0] + sv[1] + sv[2] + sv[3];
    }
    gsync(3);

    // ================= Final: block 0 only ==================================
    if (b == 0) {
        int t = threadIdx.x;
        float lf = g_lf[t], lv = g_lv[t];
        float fex, vex, ft, vt;
        blk_scan_excl<2>(lf, lv, 0.f, fex, vex, ft, vt, sf, sv);
        float lc_in = (fex != 0.f) ? 0.f : vex;       // initial l_c = 0

        float L = g_loss[t], C = g_cnt[t];
        int di = g_didx[t];
        if (di >= 0) resolve_fall(lc_in, g_dypre[t], di, th2, L, C);

#pragma unroll
        for (int d = 16; d; d >>= 1) {
            L += __shfl_down_sync(0xffffffffu, L, d);
            C += __shfl_down_sync(0xffffffffu, C, d);
        }
        __syncthreads();
        if (lane == 0) { sf[w] = L; sv[w] = C; }
        __syncthreads();
        if (t == 0 && out_size >= 4 * SEQ + 2) {
            out[4 * SEQ]     = sf[0] + sf[1] + sf[2] + sf[3];
            out[4 * SEQ + 1] = sv[0] + sv[1] + sv[2] + sv[3];
        }
        __syncthreads();
    }

    // ================= Barrier reset protocol (graph-replay safe) ==========
    if (threadIdx.x == 0) {
        __threadfence();
        atomicAdd(&g_ack, 1u);
        if (b == 0) {
            volatile unsigned* pa = &g_ack;
            while (*pa < (unsigned)NB) { }
            g_sync[0] = 0; g_sync[1] = 0; g_sync[2] = 0; g_sync[3] = 0;
            g_ack = 0;
            __threadfence();
        }
    }
}

// ---------------------------------------------------------------------------
extern "C" void kernel_launch(void* const* d_in, const int* in_sizes, int n_in,
                              void* d_out, int out_size) {
    const float* h      = (const float*)d_in[0];
    const float* W      = (const float*)d_in[1];
    const float* b      = (const float*)d_in[2];
    // d_in[3] = u (unused in outputs/loss)
    const float* u_pred = (const float*)d_in[4];
    const float* label  = (const float*)d_in[5];
    const float* thres2 = (const float*)d_in[6];
    float* out = (float*)d_out;

    gemv_sigmoid_kernel<<<SEQ / 8, 256>>>(h, W, b);
    k_scan_fused<<<NB, TPB>>>(u_pred, label, thres2, out, out_size);
}